// round 1
// baseline (speedup 1.0000x reference)
#include <cuda_runtime.h>
#include <math.h>

#define BATCH   64
#define TOKENS  4096
#define SLOTS   64
#define ADIM    32
#define EDIM    64

#define TILE_T        128
#define NCHUNK        2
#define BLOCKS_PER_B  16   // BLOCKS_PER_B * NCHUNK * TILE_T == TOKENS

// ---- device scratch (no allocations allowed) ----
__device__ float g_P[BATCH * SLOTS * EDIM];   // sum_t ww[t,s] * x[t,d]
__device__ float g_W[BATCH * SLOTS];          // sum_t ww[t,s]
__device__ float g_A[SLOTS * ADIM];           // normalized addresses * (1/temp)

// Shared memory layout (floats) for main kernel
#define SM_XS    (TILE_T * EDIM)      // 8192
#define SM_WW    (TILE_T * SLOTS)     // 8192
#define SM_WQT   (EDIM * ADIM)        // 2048
#define SM_A2T   (ADIM * SLOTS)       // 2048
#define SM_WG    (EDIM)               // 64
#define SMEM_FLOATS (SM_XS + SM_WW + SM_WQT + SM_A2T + SM_WG)
#define SMEM_BYTES  (SMEM_FLOATS * 4)

// ============================================================
// Kernel 0: zero scratch + normalize memory_addresses (*4 = 1/temp)
// ============================================================
__global__ void prep_kernel(const float* __restrict__ addr) {
    int tid = blockIdx.x * blockDim.x + threadIdx.x;
    if (tid < BATCH * SLOTS * EDIM) g_P[tid] = 0.0f;
    if (tid < BATCH * SLOTS)        g_W[tid] = 0.0f;
    if (tid < SLOTS) {
        float ss = 0.0f;
        #pragma unroll
        for (int a = 0; a < ADIM; a++) {
            float v = addr[tid * ADIM + a];
            ss += v * v;
        }
        float r = 4.0f / fmaxf(sqrtf(ss), 1e-12f);   // 1/WRITE_TEMPERATURE folded in
        #pragma unroll
        for (int a = 0; a < ADIM; a++)
            g_A[tid * ADIM + a] = addr[tid * ADIM + a] * r;
    }
}

// ============================================================
// Kernel 1: per-token scoring (softmax * gate) + P accumulation
// grid (BLOCKS_PER_B, BATCH), 256 threads
// ============================================================
__global__ __launch_bounds__(256, 2)
void main_kernel(const float* __restrict__ x,
                 const float* __restrict__ Wq,
                 const float* __restrict__ Wg,
                 const float* __restrict__ bg)
{
    extern __shared__ float smem[];
    float* xs  = smem;                 // [TILE_T][EDIM]
    float* ww  = xs  + SM_XS;          // [TILE_T][SLOTS]
    float* wqt = ww  + SM_WW;          // [EDIM][ADIM]  (WqT[d][a])
    float* a2t = wqt + SM_WQT;         // [ADIM][SLOTS] (4*a_norm[s][a] transposed)
    float* wgs = a2t + SM_A2T;         // [EDIM]

    const int tid  = threadIdx.x;
    const int b    = blockIdx.y;
    const int lane = tid & 31;
    const int warp = tid >> 5;

    // ---- load constants into shared ----
    for (int i = tid; i < EDIM * ADIM; i += 256) {
        int a = i >> 6, d = i & 63;              // Wq is [a][d], a-major
        wqt[d * ADIM + a] = Wq[i];
    }
    for (int i = tid; i < ADIM * SLOTS; i += 256) {
        int s = i >> 5, a = i & 31;              // g_A is [s][a]
        a2t[a * SLOTS + s] = g_A[i];
    }
    if (tid < EDIM) wgs[tid] = Wg[tid];
    const float bgv = bg[0];

    const int ty = tid >> 4;   // 0..15 -> slot group (4 slots)
    const int tx = tid & 15;   // 0..15 -> embed group (4 dims)

    float acc[4][4];
    #pragma unroll
    for (int i = 0; i < 4; i++)
        #pragma unroll
        for (int j = 0; j < 4; j++) acc[i][j] = 0.0f;

    float wacc0 = 0.0f, wacc1 = 0.0f;

    float4* xs4 = (float4*)xs;
    const float4* ww4 = (const float4*)ww;

    for (int chunk = 0; chunk < NCHUNK; chunk++) {
        const int tbase = (blockIdx.x * NCHUNK + chunk) * TILE_T;
        __syncthreads();   // protect xs/ww from previous iteration's readers

        // ---- load x tile (coalesced float4) ----
        const float4* xg4 = (const float4*)(x + ((size_t)b * TOKENS + tbase) * EDIM);
        #pragma unroll
        for (int k = 0; k < (TILE_T * EDIM / 4) / 256; k++)
            xs4[tid + k * 256] = xg4[tid + k * 256];
        __syncthreads();

        // ---- phase A: scoring, one warp per token ----
        #pragma unroll 1
        for (int it = 0; it < TILE_T / 8; it++) {
            const int t = warp * (TILE_T / 8) + it;
            const float* xrow = xs + t * EDIM;
            const float xa = xrow[lane], xb = xrow[lane + 32];
            float gp = xa * wgs[lane] + xb * wgs[lane + 32];

            // q[lane] = sum_d x[d] * Wq[lane][d]   (4 accumulators for ILP)
            float q0 = 0.f, q1 = 0.f, q2 = 0.f, q3 = 0.f;
            #pragma unroll
            for (int d = 0; d < EDIM; d += 4) {
                q0 += xrow[d]     * wqt[(d)     * ADIM + lane];
                q1 += xrow[d + 1] * wqt[(d + 1) * ADIM + lane];
                q2 += xrow[d + 2] * wqt[(d + 2) * ADIM + lane];
                q3 += xrow[d + 3] * wqt[(d + 3) * ADIM + lane];
            }
            float q = (q0 + q1) + (q2 + q3);

            // warp-allreduce ||q||^2 and gate logit together
            float s2 = q * q;
            #pragma unroll
            for (int o = 16; o; o >>= 1) {
                s2 += __shfl_xor_sync(0xffffffffu, s2, o);
                gp += __shfl_xor_sync(0xffffffffu, gp, o);
            }
            const float qn = q * (1.0f / fmaxf(sqrtf(s2), 1e-12f));

            // scores for s=lane and s=lane+32 (a2t already has *4 = 1/temp)
            float sc0 = 0.f, sc1 = 0.f;
            #pragma unroll
            for (int a = 0; a < ADIM; a++) {
                const float qv = __shfl_sync(0xffffffffu, qn, a);
                sc0 += qv * a2t[a * SLOTS + lane];
                sc1 += qv * a2t[a * SLOTS + lane + 32];
            }

            // softmax over 64 slots (2 per lane)
            float m = fmaxf(sc0, sc1);
            #pragma unroll
            for (int o = 16; o; o >>= 1)
                m = fmaxf(m, __shfl_xor_sync(0xffffffffu, m, o));
            const float e0 = __expf(sc0 - m);
            const float e1 = __expf(sc1 - m);
            float z = e0 + e1;
            #pragma unroll
            for (int o = 16; o; o >>= 1)
                z += __shfl_xor_sync(0xffffffffu, z, o);

            const float gate = 1.0f / (1.0f + __expf(-(gp + bgv)));
            const float c = gate / z;
            const float w0 = e0 * c, w1 = e1 * c;
            ww[t * SLOTS + lane]      = w0;
            ww[t * SLOTS + lane + 32] = w1;
            wacc0 += w0;
            wacc1 += w1;
        }
        __syncthreads();

        // ---- phase B: P[s,e] += sum_t ww[t,s] * x[t,e], 4x4 register tile ----
        #pragma unroll 4
        for (int t = 0; t < TILE_T; t++) {
            const float4 wv = ww4[t * (SLOTS / 4) + ty];
            const float4 xv = xs4[t * (EDIM / 4) + tx];
            acc[0][0] += wv.x * xv.x; acc[0][1] += wv.x * xv.y;
            acc[0][2] += wv.x * xv.z; acc[0][3] += wv.x * xv.w;
            acc[1][0] += wv.y * xv.x; acc[1][1] += wv.y * xv.y;
            acc[1][2] += wv.y * xv.z; acc[1][3] += wv.y * xv.w;
            acc[2][0] += wv.z * xv.x; acc[2][1] += wv.z * xv.y;
            acc[2][2] += wv.z * xv.z; acc[2][3] += wv.z * xv.w;
            acc[3][0] += wv.w * xv.x; acc[3][1] += wv.w * xv.y;
            acc[3][2] += wv.w * xv.z; acc[3][3] += wv.w * xv.w;
        }
    }

    // ---- one atomic flush per block ----
    #pragma unroll
    for (int i = 0; i < 4; i++) {
        const int s = ty * 4 + i;
        #pragma unroll
        for (int j = 0; j < 4; j++)
            atomicAdd(&g_P[(b * SLOTS + s) * EDIM + tx * 4 + j], acc[i][j]);
    }
    atomicAdd(&g_W[b * SLOTS + lane],      wacc0);
    atomicAdd(&g_W[b * SLOTS + lane + 32], wacc1);
}

// ============================================================
// Kernel 2: slot_updates = (P @ Wv^T)/max(w,1e-6); blend with gates
// grid (BATCH), 256 threads. Work is tiny (17M MACs total).
// ============================================================
__global__ __launch_bounds__(256)
void finalize_kernel(const float* __restrict__ mv,
                     const float* __restrict__ Wv,
                     float* __restrict__ out)
{
    __shared__ float Pt [EDIM * 68];   // Pt[d][s], padded rows
    __shared__ float WvT[EDIM * 68];   // WvT[d][e]
    __shared__ float wsh[SLOTS];

    const int b = blockIdx.x;
    const int tid = threadIdx.x;

    for (int i = tid; i < SLOTS * EDIM; i += 256) {
        const int r = i >> 6, d = i & 63;         // i = r*64 + d
        Pt [d * 68 + r] = g_P[b * SLOTS * EDIM + i];
        WvT[d * 68 + r] = Wv[i];                  // Wv is [e][d]
    }
    if (tid < SLOTS) wsh[tid] = g_W[b * SLOTS + tid];
    __syncthreads();

    const int ty = tid >> 4, tx = tid & 15;
    float acc[4][4];
    #pragma unroll
    for (int i = 0; i < 4; i++)
        #pragma unroll
        for (int j = 0; j < 4; j++) acc[i][j] = 0.0f;

    const float4* Pt4  = (const float4*)Pt;
    const float4* WvT4 = (const float4*)WvT;
    #pragma unroll 4
    for (int d = 0; d < EDIM; d++) {
        const float4 p = Pt4 [d * 17 + ty];   // s = 4*ty..+3
        const float4 w = WvT4[d * 17 + tx];   // e = 4*tx..+3
        acc[0][0] += p.x * w.x; acc[0][1] += p.x * w.y;
        acc[0][2] += p.x * w.z; acc[0][3] += p.x * w.w;
        acc[1][0] += p.y * w.x; acc[1][1] += p.y * w.y;
        acc[1][2] += p.y * w.z; acc[1][3] += p.y * w.w;
        acc[2][0] += p.z * w.x; acc[2][1] += p.z * w.y;
        acc[2][2] += p.z * w.z; acc[2][3] += p.z * w.w;
        acc[3][0] += p.w * w.x; acc[3][1] += p.w * w.y;
        acc[3][2] += p.w * w.z; acc[3][3] += p.w * w.w;
    }

    #pragma unroll
    for (int i = 0; i < 4; i++) {
        const int s = ty * 4 + i;
        const float wv = wsh[s];
        const float em = __expf(-wv);                     // 1-g
        const float sc = (1.0f - em) / fmaxf(wv, 1e-6f);  // g / max(w,1e-6)
        const float4 m4 = ((const float4*)mv)[(b * SLOTS + s) * 16 + tx];
        float4 o;
        o.x = m4.x * em + acc[i][0] * sc;
        o.y = m4.y * em + acc[i][1] * sc;
        o.z = m4.z * em + acc[i][2] * sc;
        o.w = m4.w * em + acc[i][3] * sc;
        ((float4*)out)[(b * SLOTS + s) * 16 + tx] = o;
    }
}

// ============================================================
extern "C" void kernel_launch(void* const* d_in, const int* in_sizes, int n_in,
                              void* d_out, int out_size) {
    const float* x  = (const float*)d_in[0];
    const float* ma = (const float*)d_in[1];
    const float* mv = (const float*)d_in[2];
    const float* Wq = (const float*)d_in[3];
    const float* Wv = (const float*)d_in[4];
    const float* Wg = (const float*)d_in[5];
    const float* bg = (const float*)d_in[6];
    float* out = (float*)d_out;
    (void)in_sizes; (void)n_in; (void)out_size;

    cudaFuncSetAttribute(main_kernel,
                         cudaFuncAttributeMaxDynamicSharedMemorySize, SMEM_BYTES);

    prep_kernel<<<1024, 256>>>(ma);

    dim3 grid(BLOCKS_PER_B, BATCH);
    main_kernel<<<grid, 256, SMEM_BYTES>>>(x, Wq, Wg, bg);

    finalize_kernel<<<BATCH, 256>>>(mv, Wv, out);
}

// round 2
// speedup vs baseline: 1.5911x; 1.5911x over previous
#include <cuda_runtime.h>
#include <math.h>
#include <stdint.h>

#define BATCH   64
#define TOKENS  4096
#define SLOTS   64
#define ADIM    32
#define EDIM    64

#define TILE_T        128
#define NCHUNK        2
#define BLOCKS_PER_B  16   // BLOCKS_PER_B * NCHUNK * TILE_T == TOKENS

// padded row strides (floats)
#define RS_T 132   // for xsT[e][t], wwT[s][t]  (t fast, 128 data + 4 pad)
#define RS_Q 36    // q[t][a]   (a fast, 32 data + 4 pad)
#define RS_A 36    // a2s[s][a] (a fast)

// shared memory float offsets
#define OFF_XST 0                              // [EDIM][RS_T]  x^T  8448
#define OFF_WWT (OFF_XST + EDIM * RS_T)        // [SLOTS][RS_T] ww^T 8448
#define OFF_Q   (OFF_WWT + SLOTS * RS_T)       // [TILE_T][RS_Q]     4608
#define OFF_WQT (OFF_Q   + TILE_T * RS_Q)      // [EDIM][ADIM] Wq^T  2048
#define OFF_A2S (OFF_WQT + EDIM * ADIM)        // [SLOTS][RS_A]      2304
#define OFF_WG  (OFF_A2S + SLOTS * RS_A)       // [EDIM]             64
#define OFF_SCL (OFF_WG  + EDIM)               // [TILE_T]           128
#define OFF_GT  (OFF_SCL + TILE_T)             // [TILE_T]           128
#define SMEM_FLOATS (OFF_GT + TILE_T)
#define SMEM_BYTES  (SMEM_FLOATS * 4)          // 104704 B -> 2 CTAs/SM

// ---- device scratch ----
__device__ float g_P[BATCH * SLOTS * EDIM];
__device__ float g_W[BATCH * SLOTS];
__device__ float g_A[SLOTS * ADIM];

// ================= f32x2 helpers =================
__device__ __forceinline__ uint64_t f32x2_dup(float v) {
    uint64_t r; uint32_t u = __float_as_uint(v);
    asm("mov.b64 %0, {%1, %1};" : "=l"(r) : "r"(u));
    return r;
}
__device__ __forceinline__ void ffma2(uint64_t& d, uint64_t a, uint64_t b) {
    asm("fma.rn.f32x2 %0, %1, %2, %0;" : "+l"(d) : "l"(a), "l"(b));
}
__device__ __forceinline__ float f32x2_sum(uint64_t v) {
    double dv = __longlong_as_double((long long)v);
    return __uint_as_float((unsigned)__double2loint(dv)) +
           __uint_as_float((unsigned)__double2hiint(dv));
}
// 16B load of two packed f32 pairs
__device__ __forceinline__ void ld2u64(const float* p, uint64_t& a, uint64_t& b) {
    double2 t = *(const double2*)p;
    a = (uint64_t)__double_as_longlong(t.x);
    b = (uint64_t)__double_as_longlong(t.y);
}

// ============================================================
// Kernel 0: zero scratch + normalize memory_addresses (*4 = 1/temp)
// ============================================================
__global__ void prep_kernel(const float* __restrict__ addr) {
    int tid = blockIdx.x * blockDim.x + threadIdx.x;
    if (tid < BATCH * SLOTS * EDIM) g_P[tid] = 0.0f;
    if (tid < BATCH * SLOTS)        g_W[tid] = 0.0f;
    if (tid < SLOTS) {
        float ss = 0.0f;
        #pragma unroll
        for (int a = 0; a < ADIM; a++) {
            float v = addr[tid * ADIM + a];
            ss += v * v;
        }
        float r = 4.0f / fmaxf(sqrtf(ss), 1e-12f);   // 1/WRITE_TEMPERATURE folded in
        #pragma unroll
        for (int a = 0; a < ADIM; a++)
            g_A[tid * ADIM + a] = addr[tid * ADIM + a] * r;
    }
}

// ============================================================
// Kernel 1: GEMM-ized scoring + P accumulation
// grid (BLOCKS_PER_B, BATCH), 256 threads
// ============================================================
__global__ __launch_bounds__(256, 2)
void main_kernel(const float* __restrict__ x,
                 const float* __restrict__ Wq,
                 const float* __restrict__ Wg,
                 const float* __restrict__ bg)
{
    extern __shared__ float sm[];
    const int tid = threadIdx.x;
    const int b   = blockIdx.y;

    // ---- constants into shared ----
    for (int i = tid; i < ADIM * EDIM; i += 256) {
        int a = i >> 6, d = i & 63;                  // Wq is [a][d]
        sm[OFF_WQT + d * ADIM + a] = Wq[i];          // WqT[d][a]
    }
    for (int i = tid; i < SLOTS * ADIM; i += 256) {
        int s = i >> 5, a = i & 31;
        sm[OFF_A2S + s * RS_A + a] = g_A[i];         // a2s[s][a] (already *4/norm)
    }
    if (tid < EDIM) sm[OFF_WG + tid] = Wg[tid];
    const float bgv = bg[0];

    // thread mappings
    const int tm = tid >> 3;     // 0..31 : token group (4 tokens) for Q/S GEMMs
    const int an = tid & 7;      // 0..7  : a-group (Q) / s-lane (S)
    const int sy = tid >> 4;     // 0..15 : slot group (4 slots) for phase B
    const int ex = tid & 15;     // 0..15 : embed lane for phase B (e = j*16+ex)

    // persistent phase-B accumulators (pairs over t)
    uint64_t accB[4][4];
    #pragma unroll
    for (int i = 0; i < 4; i++)
        #pragma unroll
        for (int j = 0; j < 4; j++) accB[i][j] = 0;
    float wacc = 0.0f;   // threads 0..63: sum_t ww[t][slot=tid]

    for (int chunk = 0; chunk < NCHUNK; chunk++) {
        const int tbase = (blockIdx.x * NCHUNK + chunk) * TILE_T;
        __syncthreads();   // previous chunk's readers of xsT/wwT done

        // ---- load x tile, store transposed xsT[d][t] ----
        const float4* xg4 = (const float4*)(x + ((size_t)b * TOKENS + tbase) * EDIM);
        #pragma unroll
        for (int k = 0; k < 8; k++) {
            int f = tid + k * 256;           // float4 index in [0,2048)
            float4 v = xg4[f];
            int t = f >> 4, dg = (f & 15) * 4;
            sm[OFF_XST + (dg + 0) * RS_T + t] = v.x;
            sm[OFF_XST + (dg + 1) * RS_T + t] = v.y;
            sm[OFF_XST + (dg + 2) * RS_T + t] = v.z;
            sm[OFF_XST + (dg + 3) * RS_T + t] = v.w;
        }
        __syncthreads();

        // ---- Q-GEMM: q[t][a] = sum_d xsT[d][t] * WqT[d][a] ----
        {
            uint64_t acc[4][2];
            #pragma unroll
            for (int i = 0; i < 4; i++) { acc[i][0] = 0; acc[i][1] = 0; }
            #pragma unroll 4
            for (int k = 0; k < EDIM; k++) {
                float4 xv = *(const float4*)&sm[OFF_XST + k * RS_T + tm * 4];
                uint64_t w0, w1;
                ld2u64(&sm[OFF_WQT + k * ADIM + an * 4], w0, w1);
                uint64_t x0 = f32x2_dup(xv.x), x1 = f32x2_dup(xv.y);
                uint64_t x2 = f32x2_dup(xv.z), x3 = f32x2_dup(xv.w);
                ffma2(acc[0][0], x0, w0); ffma2(acc[0][1], x0, w1);
                ffma2(acc[1][0], x1, w0); ffma2(acc[1][1], x1, w1);
                ffma2(acc[2][0], x2, w0); ffma2(acc[2][1], x2, w1);
                ffma2(acc[3][0], x3, w0); ffma2(acc[3][1], x3, w1);
            }
            #pragma unroll
            for (int i = 0; i < 4; i++) {
                *(double*)&sm[OFF_Q + (tm * 4 + i) * RS_Q + an * 4]     =
                    __longlong_as_double((long long)acc[i][0]);
                *(double*)&sm[OFF_Q + (tm * 4 + i) * RS_Q + an * 4 + 2] =
                    __longlong_as_double((long long)acc[i][1]);
            }
        }
        __syncthreads();

        // ---- norm scale + gate per token ----
        if (tid < TILE_T) {
            const float* qr = &sm[OFF_Q + tid * RS_Q];
            float ss = 0.0f;
            #pragma unroll
            for (int a4 = 0; a4 < ADIM; a4 += 4) {
                float4 v = *(const float4*)(qr + a4);
                ss += v.x * v.x + v.y * v.y + v.z * v.z + v.w * v.w;
            }
            sm[OFF_SCL + tid] = 1.0f / fmaxf(sqrtf(ss), 1e-12f);
            float gp = 0.0f;
            #pragma unroll 16
            for (int d = 0; d < EDIM; d++)
                gp += sm[OFF_XST + d * RS_T + tid] * sm[OFF_WG + d];
            sm[OFF_GT + tid] = 1.0f / (1.0f + __expf(-(gp + bgv)));
        }
        __syncthreads();

        // ---- S-GEMM (raw scores -> wwT[s][t]), two j-half passes ----
        #pragma unroll
        for (int jb = 0; jb < 8; jb += 4) {
            uint64_t acc[4][4];
            #pragma unroll
            for (int i = 0; i < 4; i++)
                #pragma unroll
                for (int j = 0; j < 4; j++) acc[i][j] = 0;
            #pragma unroll
            for (int ka = 0; ka < ADIM; ka += 4) {
                uint64_t ap[4][2];
                #pragma unroll
                for (int j = 0; j < 4; j++)
                    ld2u64(&sm[OFF_A2S + ((jb + j) * 8 + an) * RS_A + ka],
                           ap[j][0], ap[j][1]);
                #pragma unroll
                for (int i = 0; i < 4; i++) {
                    uint64_t q0, q1;
                    ld2u64(&sm[OFF_Q + (tm * 4 + i) * RS_Q + ka], q0, q1);
                    #pragma unroll
                    for (int j = 0; j < 4; j++) {
                        ffma2(acc[i][j], q0, ap[j][0]);
                        ffma2(acc[i][j], q1, ap[j][1]);
                    }
                }
            }
            #pragma unroll
            for (int i = 0; i < 4; i++)
                #pragma unroll
                for (int j = 0; j < 4; j++)
                    sm[OFF_WWT + ((jb + j) * 8 + an) * RS_T + tm * 4 + i] =
                        f32x2_sum(acc[i][j]);
        }
        __syncthreads();

        // ---- softmax per token (column of wwT), in place ----
        // scores bounded by |4*qhat.ahat| <= 4 -> exp safe without max-subtract
        if (tid < TILE_T) {
            const float scl = sm[OFF_SCL + tid];
            float z = 0.0f;
            #pragma unroll 8
            for (int s = 0; s < SLOTS; s++) {
                float e = __expf(sm[OFF_WWT + s * RS_T + tid] * scl);
                sm[OFF_WWT + s * RS_T + tid] = e;
                z += e;
            }
            const float c = sm[OFF_GT + tid] / z;
            #pragma unroll 8
            for (int s = 0; s < SLOTS; s++)
                sm[OFF_WWT + s * RS_T + tid] *= c;
        }
        __syncthreads();

        // ---- slot-weight row sums (threads 0..63), read-only on wwT ----
        if (tid < SLOTS) {
            const float* wr = &sm[OFF_WWT + tid * RS_T];
            float s0 = 0.0f;
            #pragma unroll 8
            for (int t = 0; t < TILE_T; t += 4) {
                float4 v = *(const float4*)(wr + t);
                s0 += v.x + v.y + v.z + v.w;
            }
            wacc += s0;
        }

        // ---- phase B: P[s][e] += sum_t wwT[s][t] * xsT[e][t] (pairs over t) ----
        #pragma unroll 2
        for (int t = 0; t < TILE_T; t += 4) {
            uint64_t xp[4][2];
            #pragma unroll
            for (int j = 0; j < 4; j++)
                ld2u64(&sm[OFF_XST + (j * 16 + ex) * RS_T + t], xp[j][0], xp[j][1]);
            #pragma unroll
            for (int i = 0; i < 4; i++) {
                uint64_t w0, w1;
                ld2u64(&sm[OFF_WWT + (sy * 4 + i) * RS_T + t], w0, w1);
                #pragma unroll
                for (int j = 0; j < 4; j++) {
                    ffma2(accB[i][j], w0, xp[j][0]);
                    ffma2(accB[i][j], w1, xp[j][1]);
                }
            }
        }
    }

    // ---- global flush ----
    #pragma unroll
    for (int i = 0; i < 4; i++)
        #pragma unroll
        for (int j = 0; j < 4; j++)
            atomicAdd(&g_P[(b * SLOTS + sy * 4 + i) * EDIM + j * 16 + ex],
                      f32x2_sum(accB[i][j]));
    if (tid < SLOTS) atomicAdd(&g_W[b * SLOTS + tid], wacc);
}

// ============================================================
// Kernel 2: slot_updates = (P @ Wv^T)/max(w,1e-6); blend with gates
// ============================================================
__global__ __launch_bounds__(256)
void finalize_kernel(const float* __restrict__ mv,
                     const float* __restrict__ Wv,
                     float* __restrict__ out)
{
    __shared__ float Pt [EDIM * 68];   // Pt[d][s]
    __shared__ float WvT[EDIM * 68];   // WvT[d][e]
    __shared__ float wsh[SLOTS];

    const int b = blockIdx.x;
    const int tid = threadIdx.x;

    for (int i = tid; i < SLOTS * EDIM; i += 256) {
        const int r = i >> 6, d = i & 63;
        Pt [d * 68 + r] = g_P[b * SLOTS * EDIM + i];
        WvT[d * 68 + r] = Wv[i];
    }
    if (tid < SLOTS) wsh[tid] = g_W[b * SLOTS + tid];
    __syncthreads();

    const int ty = tid >> 4, tx = tid & 15;
    float acc[4][4];
    #pragma unroll
    for (int i = 0; i < 4; i++)
        #pragma unroll
        for (int j = 0; j < 4; j++) acc[i][j] = 0.0f;

    const float4* Pt4  = (const float4*)Pt;
    const float4* WvT4 = (const float4*)WvT;
    #pragma unroll 4
    for (int d = 0; d < EDIM; d++) {
        const float4 p = Pt4 [d * 17 + ty];
        const float4 w = WvT4[d * 17 + tx];
        acc[0][0] += p.x * w.x; acc[0][1] += p.x * w.y;
        acc[0][2] += p.x * w.z; acc[0][3] += p.x * w.w;
        acc[1][0] += p.y * w.x; acc[1][1] += p.y * w.y;
        acc[1][2] += p.y * w.z; acc[1][3] += p.y * w.w;
        acc[2][0] += p.z * w.x; acc[2][1] += p.z * w.y;
        acc[2][2] += p.z * w.z; acc[2][3] += p.z * w.w;
        acc[3][0] += p.w * w.x; acc[3][1] += p.w * w.y;
        acc[3][2] += p.w * w.z; acc[3][3] += p.w * w.w;
    }

    #pragma unroll
    for (int i = 0; i < 4; i++) {
        const int s = ty * 4 + i;
        const float wv = wsh[s];
        const float em = __expf(-wv);                     // 1-g
        const float sc = (1.0f - em) / fmaxf(wv, 1e-6f);  // g / max(w,1e-6)
        const float4 m4 = ((const float4*)mv)[(b * SLOTS + s) * 16 + tx];
        float4 o;
        o.x = m4.x * em + acc[i][0] * sc;
        o.y = m4.y * em + acc[i][1] * sc;
        o.z = m4.z * em + acc[i][2] * sc;
        o.w = m4.w * em + acc[i][3] * sc;
        ((float4*)out)[(b * SLOTS + s) * 16 + tx] = o;
    }
}

// ============================================================
extern "C" void kernel_launch(void* const* d_in, const int* in_sizes, int n_in,
                              void* d_out, int out_size) {
    const float* x  = (const float*)d_in[0];
    const float* ma = (const float*)d_in[1];
    const float* mv = (const float*)d_in[2];
    const float* Wq = (const float*)d_in[3];
    const float* Wv = (const float*)d_in[4];
    const float* Wg = (const float*)d_in[5];
    const float* bg = (const float*)d_in[6];
    float* out = (float*)d_out;
    (void)in_sizes; (void)n_in; (void)out_size;

    cudaFuncSetAttribute(main_kernel,
                         cudaFuncAttributeMaxDynamicSharedMemorySize, SMEM_BYTES);

    prep_kernel<<<1024, 256>>>(ma);

    dim3 grid(BLOCKS_PER_B, BATCH);
    main_kernel<<<grid, 256, SMEM_BYTES>>>(x, Wq, Wg, bg);

    finalize_kernel<<<BATCH, 256>>>(mv, Wv, out);
}

// round 3
// speedup vs baseline: 1.5967x; 1.0035x over previous
#include <cuda_runtime.h>
#include <math.h>
#include <stdint.h>

#define BATCH   64
#define TOKENS  4096
#define SLOTS   64
#define ADIM    32
#define EDIM    64

#define TILE_T        128
#define NCHUNK        2
#define BLOCKS_PER_B  16   // BLOCKS_PER_B * NCHUNK * TILE_T == TOKENS

// padded row strides (floats)
#define RS_T 132   // for xsT[e][t], wwT[s][t]  (t fast, 128 data + 4 pad)
#define RS_Q 36    // q[t][a]   (a fast, 32 data + 4 pad)
#define RS_A 36    // a2s[s][a] (a fast)

// shared memory float offsets
#define OFF_XST 0                              // [EDIM][RS_T]  x^T  8448
#define OFF_WWT (OFF_XST + EDIM * RS_T)        // [SLOTS][RS_T] ww^T 8448
#define OFF_Q   (OFF_WWT + SLOTS * RS_T)       // [TILE_T][RS_Q]     4608
#define OFF_WQT (OFF_Q   + TILE_T * RS_Q)      // [EDIM][ADIM] Wq^T  2048
#define OFF_A2S (OFF_WQT + EDIM * ADIM)        // [SLOTS][RS_A]      2304
#define OFF_WG  (OFF_A2S + SLOTS * RS_A)       // [EDIM]             64
#define OFF_SCL (OFF_WG  + EDIM)               // [TILE_T]           128
#define OFF_GT  (OFF_SCL + TILE_T)             // [TILE_T]           128
#define SMEM_FLOATS (OFF_GT + TILE_T)
#define SMEM_BYTES  (SMEM_FLOATS * 4)          // 104704 B -> 2 CTAs/SM

// ---- device scratch ----
__device__ float g_P[BATCH * SLOTS * EDIM];
__device__ float g_W[BATCH * SLOTS];
__device__ float g_A[SLOTS * ADIM];

// ================= f32x2 helpers =================
__device__ __forceinline__ uint64_t f32x2_dup(float v) {
    uint64_t r; uint32_t u = __float_as_uint(v);
    asm("mov.b64 %0, {%1, %1};" : "=l"(r) : "r"(u));
    return r;
}
__device__ __forceinline__ void ffma2(uint64_t& d, uint64_t a, uint64_t b) {
    asm("fma.rn.f32x2 %0, %1, %2, %0;" : "+l"(d) : "l"(a), "l"(b));
}
__device__ __forceinline__ float f32x2_sum(uint64_t v) {
    double dv = __longlong_as_double((long long)v);
    return __uint_as_float((unsigned)__double2loint(dv)) +
           __uint_as_float((unsigned)__double2hiint(dv));
}
// 16B load of two packed f32 pairs
__device__ __forceinline__ void ld2u64(const float* p, uint64_t& a, uint64_t& b) {
    double2 t = *(const double2*)p;
    a = (uint64_t)__double_as_longlong(t.x);
    b = (uint64_t)__double_as_longlong(t.y);
}

// ============================================================
// Kernel 0: zero scratch + normalize memory_addresses (*4 = 1/temp)
// ============================================================
__global__ void prep_kernel(const float* __restrict__ addr) {
    int tid = blockIdx.x * blockDim.x + threadIdx.x;
    if (tid < BATCH * SLOTS * EDIM) g_P[tid] = 0.0f;
    if (tid < BATCH * SLOTS)        g_W[tid] = 0.0f;
    if (tid < SLOTS) {
        float ss = 0.0f;
        #pragma unroll
        for (int a = 0; a < ADIM; a++) {
            float v = addr[tid * ADIM + a];
            ss += v * v;
        }
        float r = 4.0f / fmaxf(sqrtf(ss), 1e-12f);   // 1/WRITE_TEMPERATURE folded in
        #pragma unroll
        for (int a = 0; a < ADIM; a++)
            g_A[tid * ADIM + a] = addr[tid * ADIM + a] * r;
    }
}

// ============================================================
// Kernel 1: GEMM-ized scoring + P accumulation
// grid (BLOCKS_PER_B, BATCH), 256 threads
// ============================================================
__global__ __launch_bounds__(256, 2)
void main_kernel(const float* __restrict__ x,
                 const float* __restrict__ Wq,
                 const float* __restrict__ Wg,
                 const float* __restrict__ bg)
{
    extern __shared__ float sm[];
    const int tid = threadIdx.x;
    const int b   = blockIdx.y;

    // ---- constants into shared ----
    for (int i = tid; i < ADIM * EDIM; i += 256) {
        int a = i >> 6, d = i & 63;                  // Wq is [a][d]
        sm[OFF_WQT + d * ADIM + a] = Wq[i];          // WqT[d][a]
    }
    for (int i = tid; i < SLOTS * ADIM; i += 256) {
        int s = i >> 5, a = i & 31;
        sm[OFF_A2S + s * RS_A + a] = g_A[i];         // a2s[s][a] (already *4/norm)
    }
    if (tid < EDIM) sm[OFF_WG + tid] = Wg[tid];
    const float bgv = bg[0];

    // thread mappings
    const int tm = tid >> 3;     // 0..31 : token group (4 tokens) for Q/S GEMMs
    const int an = tid & 7;      // 0..7  : a-group (Q) / s-lane (S)
    const int sy = tid >> 4;     // 0..15 : slot group (4 slots) for phase B
    const int ex = tid & 15;     // 0..15 : embed lane for phase B (e = j*16+ex)

    // persistent phase-B accumulators (pairs over t)
    uint64_t accB[4][4];
    #pragma unroll
    for (int i = 0; i < 4; i++)
        #pragma unroll
        for (int j = 0; j < 4; j++) accB[i][j] = 0;
    float wacc = 0.0f;   // threads 0..63: sum_t ww[t][slot=tid]

    for (int chunk = 0; chunk < NCHUNK; chunk++) {
        const int tbase = (blockIdx.x * NCHUNK + chunk) * TILE_T;
        __syncthreads();   // previous chunk's readers of xsT/wwT done

        // ---- load x tile, store transposed xsT[d][t] ----
        const float4* xg4 = (const float4*)(x + ((size_t)b * TOKENS + tbase) * EDIM);
        #pragma unroll
        for (int k = 0; k < 8; k++) {
            int f = tid + k * 256;           // float4 index in [0,2048)
            float4 v = xg4[f];
            int t = f >> 4, dg = (f & 15) * 4;
            sm[OFF_XST + (dg + 0) * RS_T + t] = v.x;
            sm[OFF_XST + (dg + 1) * RS_T + t] = v.y;
            sm[OFF_XST + (dg + 2) * RS_T + t] = v.z;
            sm[OFF_XST + (dg + 3) * RS_T + t] = v.w;
        }
        __syncthreads();

        // ---- Q-GEMM: q[t][a] = sum_d xsT[d][t] * WqT[d][a] ----
        {
            uint64_t acc[4][2];
            #pragma unroll
            for (int i = 0; i < 4; i++) { acc[i][0] = 0; acc[i][1] = 0; }
            #pragma unroll 4
            for (int k = 0; k < EDIM; k++) {
                float4 xv = *(const float4*)&sm[OFF_XST + k * RS_T + tm * 4];
                uint64_t w0, w1;
                ld2u64(&sm[OFF_WQT + k * ADIM + an * 4], w0, w1);
                uint64_t x0 = f32x2_dup(xv.x), x1 = f32x2_dup(xv.y);
                uint64_t x2 = f32x2_dup(xv.z), x3 = f32x2_dup(xv.w);
                ffma2(acc[0][0], x0, w0); ffma2(acc[0][1], x0, w1);
                ffma2(acc[1][0], x1, w0); ffma2(acc[1][1], x1, w1);
                ffma2(acc[2][0], x2, w0); ffma2(acc[2][1], x2, w1);
                ffma2(acc[3][0], x3, w0); ffma2(acc[3][1], x3, w1);
            }
            #pragma unroll
            for (int i = 0; i < 4; i++) {
                *(double*)&sm[OFF_Q + (tm * 4 + i) * RS_Q + an * 4]     =
                    __longlong_as_double((long long)acc[i][0]);
                *(double*)&sm[OFF_Q + (tm * 4 + i) * RS_Q + an * 4 + 2] =
                    __longlong_as_double((long long)acc[i][1]);
            }
        }
        __syncthreads();

        // ---- norm scale + gate per token ----
        if (tid < TILE_T) {
            const float* qr = &sm[OFF_Q + tid * RS_Q];
            float ss = 0.0f;
            #pragma unroll
            for (int a4 = 0; a4 < ADIM; a4 += 4) {
                float4 v = *(const float4*)(qr + a4);
                ss += v.x * v.x + v.y * v.y + v.z * v.z + v.w * v.w;
            }
            sm[OFF_SCL + tid] = 1.0f / fmaxf(sqrtf(ss), 1e-12f);
            float gp = 0.0f;
            #pragma unroll 16
            for (int d = 0; d < EDIM; d++)
                gp += sm[OFF_XST + d * RS_T + tid] * sm[OFF_WG + d];
            sm[OFF_GT + tid] = 1.0f / (1.0f + __expf(-(gp + bgv)));
        }
        __syncthreads();

        // ---- S-GEMM (raw scores -> wwT[s][t]), two j-half passes ----
        #pragma unroll
        for (int jb = 0; jb < 8; jb += 4) {
            uint64_t acc[4][4];
            #pragma unroll
            for (int i = 0; i < 4; i++)
                #pragma unroll
                for (int j = 0; j < 4; j++) acc[i][j] = 0;
            #pragma unroll
            for (int ka = 0; ka < ADIM; ka += 4) {
                uint64_t ap[4][2];
                #pragma unroll
                for (int j = 0; j < 4; j++)
                    ld2u64(&sm[OFF_A2S + ((jb + j) * 8 + an) * RS_A + ka],
                           ap[j][0], ap[j][1]);
                #pragma unroll
                for (int i = 0; i < 4; i++) {
                    uint64_t q0, q1;
                    ld2u64(&sm[OFF_Q + (tm * 4 + i) * RS_Q + ka], q0, q1);
                    #pragma unroll
                    for (int j = 0; j < 4; j++) {
                        ffma2(acc[i][j], q0, ap[j][0]);
                        ffma2(acc[i][j], q1, ap[j][1]);
                    }
                }
            }
            #pragma unroll
            for (int i = 0; i < 4; i++)
                #pragma unroll
                for (int j = 0; j < 4; j++)
                    sm[OFF_WWT + ((jb + j) * 8 + an) * RS_T + tm * 4 + i] =
                        f32x2_sum(acc[i][j]);
        }
        __syncthreads();

        // ---- softmax per token (column of wwT), in place ----
        // scores bounded by |4*qhat.ahat| <= 4 -> exp safe without max-subtract
        if (tid < TILE_T) {
            const float scl = sm[OFF_SCL + tid];
            float z = 0.0f;
            #pragma unroll 8
            for (int s = 0; s < SLOTS; s++) {
                float e = __expf(sm[OFF_WWT + s * RS_T + tid] * scl);
                sm[OFF_WWT + s * RS_T + tid] = e;
                z += e;
            }
            const float c = sm[OFF_GT + tid] / z;
            #pragma unroll 8
            for (int s = 0; s < SLOTS; s++)
                sm[OFF_WWT + s * RS_T + tid] *= c;
        }
        __syncthreads();

        // ---- slot-weight row sums (threads 0..63), read-only on wwT ----
        if (tid < SLOTS) {
            const float* wr = &sm[OFF_WWT + tid * RS_T];
            float s0 = 0.0f;
            #pragma unroll 8
            for (int t = 0; t < TILE_T; t += 4) {
                float4 v = *(const float4*)(wr + t);
                s0 += v.x + v.y + v.z + v.w;
            }
            wacc += s0;
        }

        // ---- phase B: P[s][e] += sum_t wwT[s][t] * xsT[e][t] (pairs over t) ----
        #pragma unroll 2
        for (int t = 0; t < TILE_T; t += 4) {
            uint64_t xp[4][2];
            #pragma unroll
            for (int j = 0; j < 4; j++)
                ld2u64(&sm[OFF_XST + (j * 16 + ex) * RS_T + t], xp[j][0], xp[j][1]);
            #pragma unroll
            for (int i = 0; i < 4; i++) {
                uint64_t w0, w1;
                ld2u64(&sm[OFF_WWT + (sy * 4 + i) * RS_T + t], w0, w1);
                #pragma unroll
                for (int j = 0; j < 4; j++) {
                    ffma2(accB[i][j], w0, xp[j][0]);
                    ffma2(accB[i][j], w1, xp[j][1]);
                }
            }
        }
    }

    // ---- global flush ----
    #pragma unroll
    for (int i = 0; i < 4; i++)
        #pragma unroll
        for (int j = 0; j < 4; j++)
            atomicAdd(&g_P[(b * SLOTS + sy * 4 + i) * EDIM + j * 16 + ex],
                      f32x2_sum(accB[i][j]));
    if (tid < SLOTS) atomicAdd(&g_W[b * SLOTS + tid], wacc);
}

// ============================================================
// Kernel 2: slot_updates = (P @ Wv^T)/max(w,1e-6); blend with gates
// ============================================================
__global__ __launch_bounds__(256)
void finalize_kernel(const float* __restrict__ mv,
                     const float* __restrict__ Wv,
                     float* __restrict__ out)
{
    __shared__ float Pt [EDIM * 68];   // Pt[d][s]
    __shared__ float WvT[EDIM * 68];   // WvT[d][e]
    __shared__ float wsh[SLOTS];

    const int b = blockIdx.x;
    const int tid = threadIdx.x;

    for (int i = tid; i < SLOTS * EDIM; i += 256) {
        const int r = i >> 6, d = i & 63;
        Pt [d * 68 + r] = g_P[b * SLOTS * EDIM + i];
        WvT[d * 68 + r] = Wv[i];
    }
    if (tid < SLOTS) wsh[tid] = g_W[b * SLOTS + tid];
    __syncthreads();

    const int ty = tid >> 4, tx = tid & 15;
    float acc[4][4];
    #pragma unroll
    for (int i = 0; i < 4; i++)
        #pragma unroll
        for (int j = 0; j < 4; j++) acc[i][j] = 0.0f;

    const float4* Pt4  = (const float4*)Pt;
    const float4* WvT4 = (const float4*)WvT;
    #pragma unroll 4
    for (int d = 0; d < EDIM; d++) {
        const float4 p = Pt4 [d * 17 + ty];
        const float4 w = WvT4[d * 17 + tx];
        acc[0][0] += p.x * w.x; acc[0][1] += p.x * w.y;
        acc[0][2] += p.x * w.z; acc[0][3] += p.x * w.w;
        acc[1][0] += p.y * w.x; acc[1][1] += p.y * w.y;
        acc[1][2] += p.y * w.z; acc[1][3] += p.y * w.w;
        acc[2][0] += p.z * w.x; acc[2][1] += p.z * w.y;
        acc[2][2] += p.z * w.z; acc[2][3] += p.z * w.w;
        acc[3][0] += p.w * w.x; acc[3][1] += p.w * w.y;
        acc[3][2] += p.w * w.z; acc[3][3] += p.w * w.w;
    }

    #pragma unroll
    for (int i = 0; i < 4; i++) {
        const int s = ty * 4 + i;
        const float wv = wsh[s];
        const float em = __expf(-wv);                     // 1-g
        const float sc = (1.0f - em) / fmaxf(wv, 1e-6f);  // g / max(w,1e-6)
        const float4 m4 = ((const float4*)mv)[(b * SLOTS + s) * 16 + tx];
        float4 o;
        o.x = m4.x * em + acc[i][0] * sc;
        o.y = m4.y * em + acc[i][1] * sc;
        o.z = m4.z * em + acc[i][2] * sc;
        o.w = m4.w * em + acc[i][3] * sc;
        ((float4*)out)[(b * SLOTS + s) * 16 + tx] = o;
    }
}

// ============================================================
extern "C" void kernel_launch(void* const* d_in, const int* in_sizes, int n_in,
                              void* d_out, int out_size) {
    const float* x  = (const float*)d_in[0];
    const float* ma = (const float*)d_in[1];
    const float* mv = (const float*)d_in[2];
    const float* Wq = (const float*)d_in[3];
    const float* Wv = (const float*)d_in[4];
    const float* Wg = (const float*)d_in[5];
    const float* bg = (const float*)d_in[6];
    float* out = (float*)d_out;
    (void)in_sizes; (void)n_in; (void)out_size;

    cudaFuncSetAttribute(main_kernel,
                         cudaFuncAttributeMaxDynamicSharedMemorySize, SMEM_BYTES);

    prep_kernel<<<1024, 256>>>(ma);

    dim3 grid(BLOCKS_PER_B, BATCH);
    main_kernel<<<grid, 256, SMEM_BYTES>>>(x, Wq, Wg, bg);

    finalize_kernel<<<BATCH, 256>>>(mv, Wv, out);
}

// round 5
// speedup vs baseline: 3.2383x; 2.0281x over previous
#include <cuda_runtime.h>
#include <math.h>
#include <stdint.h>

#define BATCH  64
#define TOKENS 4096
#define SLOTS  64
#define ADIM   32
#define EDIM   64
#define TILE_T 128
#define NCHUNK 2
#define BPB    16     // blocks per batch; BPB*NCHUNK*TILE_T == TOKENS

// padded strides (floats)
#define PT 132        // t-contiguous rows (xts, wws)
#define PQ 36         // a-contiguous rows (qs, as_)
#define PW 68         // d-contiguous rows (wqs)

// shared float offsets
#define O_XTS 0                       // [64 d][PT]  x^T tf32
#define O_WWS (O_XTS + 64 * PT)      // [64 s][PT]  ww^T tf32
#define O_QS  (O_WWS + 64 * PT)      // [128 t][PQ] qhat tf32
#define O_WQS (O_QS  + 128 * PQ)     // [40 a][PW]  Wq rows 0-31, Wg row 32, 33-39 zero
#define O_AS  (O_WQS + 40 * PW)      // [64 s][PQ]  4*ahat tf32
#define SM_FLOATS (O_AS + 64 * PQ)
#define SM_BYTES  (SM_FLOATS * 4)    // 106112 B -> 2 CTAs/SM

__device__ float g_Ppart[BPB * BATCH * SLOTS * EDIM];   // [bx][b][s][e]
__device__ float g_Wpart[BPB * BATCH * SLOTS];

__device__ __forceinline__ float tf32r(float f) {
    uint32_t u; asm("cvt.rna.tf32.f32 %0, %1;" : "=r"(u) : "f"(f));
    return __uint_as_float(u);
}
__device__ __forceinline__ void mma8(float* c, uint32_t a0, uint32_t a1,
                                     uint32_t a2, uint32_t a3,
                                     uint32_t b0, uint32_t b1) {
    asm volatile("mma.sync.aligned.m16n8k8.row.col.f32.tf32.tf32.f32 "
        "{%0,%1,%2,%3}, {%4,%5,%6,%7}, {%8,%9}, {%0,%1,%2,%3};"
        : "+f"(c[0]), "+f"(c[1]), "+f"(c[2]), "+f"(c[3])
        : "r"(a0), "r"(a1), "r"(a2), "r"(a3), "r"(b0), "r"(b1));
}
#define U(x) __float_as_uint(x)

// ============================================================
// main: per block handles 256 tokens of one batch (2 chunks of 128)
// ============================================================
__global__ __launch_bounds__(256, 2)
void main_kernel(const float* __restrict__ x,
                 const float* __restrict__ ma,
                 const float* __restrict__ Wq,
                 const float* __restrict__ Wg,
                 const float* __restrict__ bg)
{
    extern __shared__ float sm[];
    const int tid  = threadIdx.x;
    const int bx   = blockIdx.x;   // 0..15
    const int b    = blockIdx.y;   // 0..63
    const int lane = tid & 31;
    const int warp = tid >> 5;
    const int g    = lane >> 2;    // 0..7  (row group)
    const int tc   = lane & 3;     // 0..3  (thread-in-group)
    const int m0   = warp * 16;    // token tile base for Q/S

    // ---- constants ----
    for (int i = tid; i < 40 * 64; i += 256) {
        int r = i >> 6, d = i & 63;
        float v = (r < 32) ? Wq[i] : ((r == 32) ? Wg[d] : 0.0f);
        sm[O_WQS + r * PW + d] = tf32r(v);
    }
    if (tid < SLOTS) {
        float a[ADIM]; float ss = 0.0f;
        #pragma unroll
        for (int k = 0; k < ADIM; k++) { a[k] = ma[tid * ADIM + k]; ss += a[k] * a[k]; }
        float r4 = 4.0f / fmaxf(sqrtf(ss), 1e-12f);   // 1/temperature folded
        #pragma unroll
        for (int k = 0; k < ADIM; k++)
            sm[O_AS + tid * PQ + k] = tf32r(a[k] * r4);
    }
    const float bgv = bg[0];

    // persistent P accumulators: warp covers C[16s x 32e]
    const int s0  = (warp & 3) * 16;
    const int ntb = (warp >> 2) * 4;
    float cp[4][4];
    #pragma unroll
    for (int j = 0; j < 4; j++)
        #pragma unroll
        for (int u = 0; u < 4; u++) cp[j][u] = 0.0f;
    float wsum = 0.0f;

    for (int c = 0; c < NCHUNK; c++) {
        __syncthreads();   // previous chunk's readers of xts/wws done

        // ---- load x chunk -> x^T (tf32) ----
        const float4* xg = (const float4*)(x + ((size_t)b * TOKENS + (bx * NCHUNK + c) * TILE_T) * EDIM);
        #pragma unroll
        for (int k = 0; k < 8; k++) {
            int f = tid + k * 256;            // float4 id in [0,2048)
            float4 v = xg[f];
            int t = f >> 4, d = (f & 15) * 4;
            sm[O_XTS + (d + 0) * PT + t] = tf32r(v.x);
            sm[O_XTS + (d + 1) * PT + t] = tf32r(v.y);
            sm[O_XTS + (d + 2) * PT + t] = tf32r(v.z);
            sm[O_XTS + (d + 3) * PT + t] = tf32r(v.w);
        }
        __syncthreads();

        // ============ Q-GEMM: C_q[16t x 40] = x @ [Wq;Wg]^T ============
        float cq[5][4];
        #pragma unroll
        for (int nt = 0; nt < 5; nt++)
            #pragma unroll
            for (int u = 0; u < 4; u++) cq[nt][u] = 0.0f;
        #pragma unroll
        for (int k = 0; k < 8; k++) {
            const int k8 = k * 8;
            uint32_t a0 = U(sm[O_XTS + (k8 + tc)     * PT + m0 + g]);
            uint32_t a1 = U(sm[O_XTS + (k8 + tc)     * PT + m0 + g + 8]);
            uint32_t a2 = U(sm[O_XTS + (k8 + tc + 4) * PT + m0 + g]);
            uint32_t a3 = U(sm[O_XTS + (k8 + tc + 4) * PT + m0 + g + 8]);
            #pragma unroll
            for (int nt = 0; nt < 5; nt++) {
                uint32_t b0 = U(sm[O_WQS + (nt * 8 + g) * PW + k8 + tc]);
                uint32_t b1 = U(sm[O_WQS + (nt * 8 + g) * PW + k8 + tc + 4]);
                mma8(cq[nt], a0, a1, a2, a3, b0, b1);
            }
        }
        // norms (cols 0-31) + gate (col 32)
        float ss0 = 0.f, ss1 = 0.f;
        #pragma unroll
        for (int nt = 0; nt < 4; nt++) {
            ss0 += cq[nt][0] * cq[nt][0] + cq[nt][1] * cq[nt][1];
            ss1 += cq[nt][2] * cq[nt][2] + cq[nt][3] * cq[nt][3];
        }
        ss0 += __shfl_xor_sync(0xffffffffu, ss0, 1);
        ss0 += __shfl_xor_sync(0xffffffffu, ss0, 2);
        ss1 += __shfl_xor_sync(0xffffffffu, ss1, 1);
        ss1 += __shfl_xor_sync(0xffffffffu, ss1, 2);
        const float rs0 = 1.0f / fmaxf(sqrtf(ss0), 1e-12f);
        const float rs1 = 1.0f / fmaxf(sqrtf(ss1), 1e-12f);
        const float gl0 = __shfl_sync(0xffffffffu, cq[4][0], lane & ~3);
        const float gl1 = __shfl_sync(0xffffffffu, cq[4][2], lane & ~3);
        const float gate0 = 1.0f / (1.0f + __expf(-(gl0 + bgv)));
        const float gate1 = 1.0f / (1.0f + __expf(-(gl1 + bgv)));
        // store qhat (tf32)
        #pragma unroll
        for (int nt = 0; nt < 4; nt++) {
            const int col = nt * 8 + 2 * tc;
            sm[O_QS + (m0 + g)     * PQ + col]     = tf32r(cq[nt][0] * rs0);
            sm[O_QS + (m0 + g)     * PQ + col + 1] = tf32r(cq[nt][1] * rs0);
            sm[O_QS + (m0 + g + 8) * PQ + col]     = tf32r(cq[nt][2] * rs1);
            sm[O_QS + (m0 + g + 8) * PQ + col + 1] = tf32r(cq[nt][3] * rs1);
        }
        __syncwarp();

        // ============ S-GEMM: C_s[16t x 64s] = qhat @ (4*ahat)^T ============
        float cs[8][4];
        #pragma unroll
        for (int nt = 0; nt < 8; nt++)
            #pragma unroll
            for (int u = 0; u < 4; u++) cs[nt][u] = 0.0f;
        #pragma unroll
        for (int k = 0; k < 4; k++) {
            const int k8 = k * 8;
            uint32_t a0 = U(sm[O_QS + (m0 + g)     * PQ + k8 + tc]);
            uint32_t a1 = U(sm[O_QS + (m0 + g + 8) * PQ + k8 + tc]);
            uint32_t a2 = U(sm[O_QS + (m0 + g)     * PQ + k8 + tc + 4]);
            uint32_t a3 = U(sm[O_QS + (m0 + g + 8) * PQ + k8 + tc + 4]);
            #pragma unroll
            for (int nt = 0; nt < 8; nt++) {
                uint32_t b0 = U(sm[O_AS + (nt * 8 + g) * PQ + k8 + tc]);
                uint32_t b1 = U(sm[O_AS + (nt * 8 + g) * PQ + k8 + tc + 4]);
                mma8(cs[nt], a0, a1, a2, a3, b0, b1);
            }
        }
        // softmax per token row (scores in [-4,4]; no max-subtract needed)
        float z0 = 0.f, z1 = 0.f;
        #pragma unroll
        for (int nt = 0; nt < 8; nt++) {
            cs[nt][0] = __expf(cs[nt][0]); z0 += cs[nt][0];
            cs[nt][1] = __expf(cs[nt][1]); z0 += cs[nt][1];
            cs[nt][2] = __expf(cs[nt][2]); z1 += cs[nt][2];
            cs[nt][3] = __expf(cs[nt][3]); z1 += cs[nt][3];
        }
        z0 += __shfl_xor_sync(0xffffffffu, z0, 1);
        z0 += __shfl_xor_sync(0xffffffffu, z0, 2);
        z1 += __shfl_xor_sync(0xffffffffu, z1, 1);
        z1 += __shfl_xor_sync(0xffffffffu, z1, 2);
        const float k0 = gate0 / z0, k1 = gate1 / z1;
        // store ww^T (tf32): same rounded values feed P and W => errors cancel
        #pragma unroll
        for (int nt = 0; nt < 8; nt++) {
            const int s = nt * 8 + 2 * tc;
            sm[O_WWS + s       * PT + m0 + g]     = tf32r(cs[nt][0] * k0);
            sm[O_WWS + (s + 1) * PT + m0 + g]     = tf32r(cs[nt][1] * k0);
            sm[O_WWS + s       * PT + m0 + g + 8] = tf32r(cs[nt][2] * k1);
            sm[O_WWS + (s + 1) * PT + m0 + g + 8] = tf32r(cs[nt][3] * k1);
        }
        __syncthreads();

        // ---- W partial sums from the rounded ww (threads 0..63) ----
        if (tid < SLOTS) {
            const float2* wr = (const float2*)&sm[O_WWS + tid * PT];
            float s = 0.f;
            #pragma unroll 16
            for (int t2 = 0; t2 < TILE_T / 2; t2++) { float2 v = wr[t2]; s += v.x + v.y; }
            wsum += s;
        }

        // ============ P-GEMM: cp[16s x 32e] += ww^T @ x ============
        #pragma unroll
        for (int k = 0; k < 16; k++) {
            const int k8 = k * 8;
            uint32_t a0 = U(sm[O_WWS + (s0 + g)     * PT + k8 + tc]);
            uint32_t a1 = U(sm[O_WWS + (s0 + g + 8) * PT + k8 + tc]);
            uint32_t a2 = U(sm[O_WWS + (s0 + g)     * PT + k8 + tc + 4]);
            uint32_t a3 = U(sm[O_WWS + (s0 + g + 8) * PT + k8 + tc + 4]);
            #pragma unroll
            for (int j = 0; j < 4; j++) {
                const int e = (ntb + j) * 8 + g;
                uint32_t b0 = U(sm[O_XTS + e * PT + k8 + tc]);
                uint32_t b1 = U(sm[O_XTS + e * PT + k8 + tc + 4]);
                mma8(cp[j], a0, a1, a2, a3, b0, b1);
            }
        }
    }

    // ---- flush partials (exclusive slices, no atomics) ----
    float* dst = &g_Ppart[((size_t)(bx * BATCH + b)) * SLOTS * EDIM];
    #pragma unroll
    for (int j = 0; j < 4; j++) {
        const int e = (ntb + j) * 8 + 2 * tc;
        dst[(s0 + g)     * EDIM + e]     = cp[j][0];
        dst[(s0 + g)     * EDIM + e + 1] = cp[j][1];
        dst[(s0 + g + 8) * EDIM + e]     = cp[j][2];
        dst[(s0 + g + 8) * EDIM + e + 1] = cp[j][3];
    }
    if (tid < SLOTS) g_Wpart[(bx * BATCH + b) * SLOTS + tid] = wsum;
}

// ============================================================
// finalize: sum partials, (P @ Wv^T)/max(W,1e-6), blend
// ============================================================
__global__ __launch_bounds__(256)
void finalize_kernel(const float* __restrict__ mv,
                     const float* __restrict__ Wv,
                     float* __restrict__ out)
{
    __shared__ float Pt [EDIM * 68];   // Pt[d][s]
    __shared__ float WvT[EDIM * 68];   // WvT[d][e]
    __shared__ float wsh[SLOTS];

    const int b = blockIdx.x;
    const int tid = threadIdx.x;

    for (int i = tid; i < SLOTS * EDIM; i += 256) {
        const int r = i >> 6, d = i & 63;
        float p = 0.f;
        #pragma unroll
        for (int k = 0; k < BPB; k++)
            p += g_Ppart[((size_t)(k * BATCH + b)) * SLOTS * EDIM + i];
        Pt [d * 68 + r] = p;
        WvT[d * 68 + r] = Wv[i];
    }
    if (tid < SLOTS) {
        float w = 0.f;
        #pragma unroll
        for (int k = 0; k < BPB; k++)
            w += g_Wpart[(k * BATCH + b) * SLOTS + tid];
        wsh[tid] = w;
    }
    __syncthreads();

    const int ty = tid >> 4, tx = tid & 15;
    float acc[4][4];
    #pragma unroll
    for (int i = 0; i < 4; i++)
        #pragma unroll
        for (int j = 0; j < 4; j++) acc[i][j] = 0.0f;

    const float4* Pt4  = (const float4*)Pt;
    const float4* WvT4 = (const float4*)WvT;
    #pragma unroll 4
    for (int d = 0; d < EDIM; d++) {
        const float4 p = Pt4 [d * 17 + ty];
        const float4 w = WvT4[d * 17 + tx];
        acc[0][0] += p.x * w.x; acc[0][1] += p.x * w.y;
        acc[0][2] += p.x * w.z; acc[0][3] += p.x * w.w;
        acc[1][0] += p.y * w.x; acc[1][1] += p.y * w.y;
        acc[1][2] += p.y * w.z; acc[1][3] += p.y * w.w;
        acc[2][0] += p.z * w.x; acc[2][1] += p.z * w.y;
        acc[2][2] += p.z * w.z; acc[2][3] += p.z * w.w;
        acc[3][0] += p.w * w.x; acc[3][1] += p.w * w.y;
        acc[3][2] += p.w * w.z; acc[3][3] += p.w * w.w;
    }

    #pragma unroll
    for (int i = 0; i < 4; i++) {
        const int s = ty * 4 + i;
        const float wv = wsh[s];
        const float em = __expf(-wv);                     // 1-g
        const float sc = (1.0f - em) / fmaxf(wv, 1e-6f);  // g/max(W,1e-6)
        const float4 m4 = ((const float4*)mv)[(b * SLOTS + s) * 16 + tx];
        float4 o;
        o.x = m4.x * em + acc[i][0] * sc;
        o.y = m4.y * em + acc[i][1] * sc;
        o.z = m4.z * em + acc[i][2] * sc;
        o.w = m4.w * em + acc[i][3] * sc;
        ((float4*)out)[(b * SLOTS + s) * 16 + tx] = o;
    }
}

// ============================================================
extern "C" void kernel_launch(void* const* d_in, const int* in_sizes, int n_in,
                              void* d_out, int out_size) {
    const float* x  = (const float*)d_in[0];
    const float* ma = (const float*)d_in[1];
    const float* mv = (const float*)d_in[2];
    const float* Wq = (const float*)d_in[3];
    const float* Wv = (const float*)d_in[4];
    const float* Wg = (const float*)d_in[5];
    const float* bg = (const float*)d_in[6];
    float* out = (float*)d_out;
    (void)in_sizes; (void)n_in; (void)out_size;

    cudaFuncSetAttribute(main_kernel,
                         cudaFuncAttributeMaxDynamicSharedMemorySize, SM_BYTES);

    dim3 grid(BPB, BATCH);
    main_kernel<<<grid, 256, SM_BYTES>>>(x, ma, Wq, Wg, bg);
    finalize_kernel<<<BATCH, 256>>>(mv, Wv, out);
}

// round 6
// speedup vs baseline: 3.8758x; 1.1969x over previous
#include <cuda_runtime.h>
#include <math.h>
#include <stdint.h>

#define BATCH  64
#define TOKENS 4096
#define SLOTS  64
#define ADIM   32
#define EDIM   64
#define TILE_T 128
#define NCHUNK 8
#define BPB    4      // blocks per batch; BPB*NCHUNK*TILE_T == TOKENS

// padded strides (floats): all ≡ 4 (mod 32) and 16B-multiples -> ldmatrix conflict-free
#define PT 132
#define PQ 36
#define PW 68

// shared float offsets
#define O_XTS 0                      // [64 d][PT]  x^T tf32 (XOR-swizzled chunks)
#define O_WWS (O_XTS + 64 * PT)      // [64 s][PT]  ww^T tf32 (linear)
#define O_QS  (O_WWS + 64 * PT)      // [128 t][PQ] qhat tf32
#define O_WQS (O_QS  + 128 * PQ)     // [48 a][PW]  Wq 0-31, Wg 32, 33-47 zero
#define O_AS  (O_WQS + 48 * PW)      // [64 s][PQ]  4*ahat tf32
#define SM_FLOATS (O_AS + 64 * PQ)
#define SM_BYTES  (SM_FLOATS * 4)    // 108288 B -> 2 CTAs/SM

__device__ float g_Ppart[BPB * BATCH * SLOTS * EDIM];   // [bx][b][s][e]
__device__ float g_Wpart[BPB * BATCH * SLOTS];

__device__ __forceinline__ float tf32r(float f) {
    uint32_t u; asm("cvt.rna.tf32.f32 %0, %1;" : "=r"(u) : "f"(f));
    return __uint_as_float(u);
}
__device__ __forceinline__ void mma8(float* c, uint32_t a0, uint32_t a1,
                                     uint32_t a2, uint32_t a3,
                                     uint32_t b0, uint32_t b1) {
    asm volatile("mma.sync.aligned.m16n8k8.row.col.f32.tf32.tf32.f32 "
        "{%0,%1,%2,%3}, {%4,%5,%6,%7}, {%8,%9}, {%0,%1,%2,%3};"
        : "+f"(c[0]), "+f"(c[1]), "+f"(c[2]), "+f"(c[3])
        : "r"(a0), "r"(a1), "r"(a2), "r"(a3), "r"(b0), "r"(b1));
}
__device__ __forceinline__ void ldm4(uint32_t* r, uint32_t a) {
    asm volatile("ldmatrix.sync.aligned.m8n8.x4.shared.b16 {%0,%1,%2,%3}, [%4];"
        : "=r"(r[0]), "=r"(r[1]), "=r"(r[2]), "=r"(r[3]) : "r"(a));
}
__device__ __forceinline__ uint32_t smem_u32(const void* p) {
    uint32_t a;
    asm("{ .reg .u64 t; cvta.to.shared.u64 t, %1; cvt.u32.u64 %0, t; }" : "=r"(a) : "l"(p));
    return a;
}
// XTS swizzled float index: row d, element t
__device__ __forceinline__ int xidx(int d, int t) {
    return O_XTS + d * PT + ((((t >> 2) ^ ((d >> 2) & 7)) << 2) | (t & 3));
}
#define U(x) __float_as_uint(x)

// ============================================================
// main: block handles 1024 tokens of one batch (8 chunks of 128)
// ============================================================
__global__ __launch_bounds__(256, 2)
void main_kernel(const float* __restrict__ x,
                 const float* __restrict__ ma,
                 const float* __restrict__ Wq,
                 const float* __restrict__ Wg,
                 const float* __restrict__ bg)
{
    extern __shared__ float sm[];
    const uint32_t sb = smem_u32(sm);
    const int tid  = threadIdx.x;
    const int bx   = blockIdx.x;   // 0..3
    const int b    = blockIdx.y;   // 0..63
    const int lane = tid & 31;
    const int warp = tid >> 5;
    const int g    = lane >> 2;    // 0..7
    const int tc   = lane & 3;     // 0..3
    const int m0   = warp * 16;    // token tile base

    // ---- constants ----
    for (int i = tid; i < 48 * 64; i += 256) {
        int r = i >> 6, d = i & 63;
        float v = (r < 32) ? Wq[i] : ((r == 32) ? Wg[d] : 0.0f);
        sm[O_WQS + r * PW + d] = tf32r(v);
    }
    if (tid < SLOTS) {
        float a[ADIM]; float ss = 0.0f;
        #pragma unroll
        for (int k = 0; k < ADIM; k++) { a[k] = ma[tid * ADIM + k]; ss += a[k] * a[k]; }
        float r4 = 4.0f / fmaxf(sqrtf(ss), 1e-12f);
        #pragma unroll
        for (int k = 0; k < ADIM; k++)
            sm[O_AS + tid * PQ + k] = tf32r(a[k] * r4);
    }
    const float bgv = bg[0];

    // ---- per-lane ldmatrix address bases (bytes) ----
    const int l7  = lane & 7;
    const int lml = (lane >> 3) & 1;   // +8 rows for A-type matrices 1,3
    const int lmh = lane >> 4;         // chunk+1 for A-type matrices 2,3
    const int lhi = lane >> 4;         // pair-half for B-type
    const int lcm = (lane >> 3) & 1;   // chunk sel for B-type

    const int s0  = (warp & 3) * 16;   // P-GEMM slot tile
    const int ntb = (warp >> 2) * 4;   // P-GEMM e tile base (x8)

    // A bases (linear layouts): advance k8*4 bytes per k-step
    const uint32_t aWW = sb + (uint32_t)(O_WWS + (s0 + l7 + 8 * lml) * PT + 4 * lmh) * 4;
    const uint32_t aQS = sb + (uint32_t)(O_QS  + (m0 + l7 + 8 * lml) * PQ + 4 * lmh) * 4;
    // B bases (linear layouts): jp offset added explicitly
    const uint32_t bAS = sb + (uint32_t)(O_AS  + (lhi * 8 + l7) * PQ + 4 * lcm) * 4;
    const uint32_t bWQ = sb + (uint32_t)(O_WQS + (lhi * 8 + l7) * PW + 4 * lcm) * 4;
    // B from XTS (swizzled): row bases + keys for jp=0 and jp=2
    const int rowX0 = (ntb + 0 + lhi) * 8 + l7;
    const int rowX2 = (ntb + 2 + lhi) * 8 + l7;
    const uint32_t bX0 = sb + (uint32_t)(O_XTS + rowX0 * PT) * 4;
    const uint32_t bX2 = sb + (uint32_t)(O_XTS + rowX2 * PT) * 4;
    const uint32_t keyX0 = (rowX0 >> 2) & 7, keyX2 = (rowX2 >> 2) & 7;

    // persistent P accumulators
    float cp[4][4];
    #pragma unroll
    for (int j = 0; j < 4; j++)
        #pragma unroll
        for (int u = 0; u < 4; u++) cp[j][u] = 0.0f;
    float wsum = 0.0f;

    // Q-A scalar helpers (swizzled XTS reads)
    const int tA = m0 + g, tB = m0 + g + 8;
    const int cA = tA >> 2, wA = tA & 3, cB = tB >> 2, wB = tB & 3;

    for (int c = 0; c < NCHUNK; c++) {
        __syncthreads();   // previous chunk's readers of xts/wws done

        // ---- load x chunk -> swizzled x^T (tf32) ----
        const float4* xg = (const float4*)(x + ((size_t)b * TOKENS + (bx * NCHUNK + c) * TILE_T) * EDIM);
        #pragma unroll
        for (int k = 0; k < 8; k++) {
            int f = tid + k * 256;
            float4 v = xg[f];
            int t = f >> 4, d = (f & 15) * 4;
            sm[xidx(d + 0, t)] = tf32r(v.x);
            sm[xidx(d + 1, t)] = tf32r(v.y);
            sm[xidx(d + 2, t)] = tf32r(v.z);
            sm[xidx(d + 3, t)] = tf32r(v.w);
        }
        __syncthreads();

        // ============ Q-GEMM: C_q[16t x 40] = x @ [Wq;Wg]^T ============
        float cq[5][4];
        #pragma unroll
        for (int nt = 0; nt < 5; nt++)
            #pragma unroll
            for (int u = 0; u < 4; u++) cq[nt][u] = 0.0f;
        #pragma unroll
        for (int k = 0; k < 8; k++) {
            const int k8 = k * 8;
            const int d0 = k8 + tc, d1 = k8 + tc + 4;
            const int k0 = (k8 >> 2) & 7, k1 = ((k8 >> 2) + 1) & 7;
            uint32_t a0 = U(sm[O_XTS + d0 * PT + (((cA ^ k0) << 2) | wA)]);
            uint32_t a1 = U(sm[O_XTS + d0 * PT + (((cB ^ k0) << 2) | wB)]);
            uint32_t a2 = U(sm[O_XTS + d1 * PT + (((cA ^ k1) << 2) | wA)]);
            uint32_t a3 = U(sm[O_XTS + d1 * PT + (((cB ^ k1) << 2) | wB)]);
            uint32_t bq0[4], bq1[4], bq2[4];
            ldm4(bq0, bWQ + (uint32_t)(k8 * 4));
            ldm4(bq1, bWQ + (uint32_t)(2 * 8 * PW * 4 + k8 * 4));
            ldm4(bq2, bWQ + (uint32_t)(4 * 8 * PW * 4 + k8 * 4));
            mma8(cq[0], a0, a1, a2, a3, bq0[0], bq0[1]);
            mma8(cq[1], a0, a1, a2, a3, bq0[2], bq0[3]);
            mma8(cq[2], a0, a1, a2, a3, bq1[0], bq1[1]);
            mma8(cq[3], a0, a1, a2, a3, bq1[2], bq1[3]);
            mma8(cq[4], a0, a1, a2, a3, bq2[0], bq2[1]);
        }
        // norms (cols 0-31) + gate (col 32)
        float ss0 = 0.f, ss1 = 0.f;
        #pragma unroll
        for (int nt = 0; nt < 4; nt++) {
            ss0 += cq[nt][0] * cq[nt][0] + cq[nt][1] * cq[nt][1];
            ss1 += cq[nt][2] * cq[nt][2] + cq[nt][3] * cq[nt][3];
        }
        ss0 += __shfl_xor_sync(0xffffffffu, ss0, 1);
        ss0 += __shfl_xor_sync(0xffffffffu, ss0, 2);
        ss1 += __shfl_xor_sync(0xffffffffu, ss1, 1);
        ss1 += __shfl_xor_sync(0xffffffffu, ss1, 2);
        const float rs0 = 1.0f / fmaxf(sqrtf(ss0), 1e-12f);
        const float rs1 = 1.0f / fmaxf(sqrtf(ss1), 1e-12f);
        const float gl0 = __shfl_sync(0xffffffffu, cq[4][0], lane & ~3);
        const float gl1 = __shfl_sync(0xffffffffu, cq[4][2], lane & ~3);
        const float gate0 = 1.0f / (1.0f + __expf(-(gl0 + bgv)));
        const float gate1 = 1.0f / (1.0f + __expf(-(gl1 + bgv)));
        #pragma unroll
        for (int nt = 0; nt < 4; nt++) {
            const int col = nt * 8 + 2 * tc;
            sm[O_QS + tA * PQ + col]     = tf32r(cq[nt][0] * rs0);
            sm[O_QS + tA * PQ + col + 1] = tf32r(cq[nt][1] * rs0);
            sm[O_QS + tB * PQ + col]     = tf32r(cq[nt][2] * rs1);
            sm[O_QS + tB * PQ + col + 1] = tf32r(cq[nt][3] * rs1);
        }
        __syncwarp();

        // ============ S-GEMM: C_s[16t x 64s] = qhat @ (4*ahat)^T ============
        float cs[8][4];
        #pragma unroll
        for (int nt = 0; nt < 8; nt++)
            #pragma unroll
            for (int u = 0; u < 4; u++) cs[nt][u] = 0.0f;
        #pragma unroll
        for (int k = 0; k < 4; k++) {
            const int k8 = k * 8;
            uint32_t aq[4];
            ldm4(aq, aQS + (uint32_t)(k8 * 4));
            #pragma unroll
            for (int jp = 0; jp < 4; jp++) {
                uint32_t bs[4];
                ldm4(bs, bAS + (uint32_t)(jp * 2 * 8 * PQ * 4 + k8 * 4));
                mma8(cs[jp * 2],     aq[0], aq[1], aq[2], aq[3], bs[0], bs[1]);
                mma8(cs[jp * 2 + 1], aq[0], aq[1], aq[2], aq[3], bs[2], bs[3]);
            }
        }
        // softmax (scores in [-4,4]; no max-subtract)
        float z0 = 0.f, z1 = 0.f;
        #pragma unroll
        for (int nt = 0; nt < 8; nt++) {
            cs[nt][0] = __expf(cs[nt][0]); z0 += cs[nt][0];
            cs[nt][1] = __expf(cs[nt][1]); z0 += cs[nt][1];
            cs[nt][2] = __expf(cs[nt][2]); z1 += cs[nt][2];
            cs[nt][3] = __expf(cs[nt][3]); z1 += cs[nt][3];
        }
        z0 += __shfl_xor_sync(0xffffffffu, z0, 1);
        z0 += __shfl_xor_sync(0xffffffffu, z0, 2);
        z1 += __shfl_xor_sync(0xffffffffu, z1, 1);
        z1 += __shfl_xor_sync(0xffffffffu, z1, 2);
        const float k0 = gate0 / z0, k1 = gate1 / z1;
        #pragma unroll
        for (int nt = 0; nt < 8; nt++) {
            const int s = nt * 8 + 2 * tc;
            sm[O_WWS + s       * PT + tA] = tf32r(cs[nt][0] * k0);
            sm[O_WWS + (s + 1) * PT + tA] = tf32r(cs[nt][1] * k0);
            sm[O_WWS + s       * PT + tB] = tf32r(cs[nt][2] * k1);
            sm[O_WWS + (s + 1) * PT + tB] = tf32r(cs[nt][3] * k1);
        }
        __syncthreads();

        // ---- W partial sums (threads 0..63) ----
        if (tid < SLOTS) {
            const float2* wr = (const float2*)&sm[O_WWS + tid * PT];
            float s = 0.f;
            #pragma unroll 16
            for (int t2 = 0; t2 < TILE_T / 2; t2++) { float2 v = wr[t2]; s += v.x + v.y; }
            wsum += s;
        }

        // ============ P-GEMM: cp[16s x 32e] += ww^T @ x ============
        #pragma unroll
        for (int k = 0; k < 16; k++) {
            const int k8 = k * 8;
            uint32_t ap[4], b0[4], b1[4];
            ldm4(ap, aWW + (uint32_t)(k8 * 4));
            const uint32_t ch = (uint32_t)((k8 >> 2) + lcm);
            ldm4(b0, bX0 + ((ch ^ keyX0) << 4));
            ldm4(b1, bX2 + ((ch ^ keyX2) << 4));
            mma8(cp[0], ap[0], ap[1], ap[2], ap[3], b0[0], b0[1]);
            mma8(cp[1], ap[0], ap[1], ap[2], ap[3], b0[2], b0[3]);
            mma8(cp[2], ap[0], ap[1], ap[2], ap[3], b1[0], b1[1]);
            mma8(cp[3], ap[0], ap[1], ap[2], ap[3], b1[2], b1[3]);
        }
    }

    // ---- flush partials (exclusive slices) ----
    float* dst = &g_Ppart[((size_t)(bx * BATCH + b)) * SLOTS * EDIM];
    #pragma unroll
    for (int j = 0; j < 4; j++) {
        const int e = (ntb + j) * 8 + 2 * tc;
        dst[(s0 + g)     * EDIM + e]     = cp[j][0];
        dst[(s0 + g)     * EDIM + e + 1] = cp[j][1];
        dst[(s0 + g + 8) * EDIM + e]     = cp[j][2];
        dst[(s0 + g + 8) * EDIM + e + 1] = cp[j][3];
    }
    if (tid < SLOTS) g_Wpart[(bx * BATCH + b) * SLOTS + tid] = wsum;
}

// ============================================================
// finalize: grid (BATCH, 2), each block = 32 slots of one batch
// ============================================================
__global__ __launch_bounds__(256)
void finalize_kernel(const float* __restrict__ mv,
                     const float* __restrict__ Wv,
                     float* __restrict__ out)
{
    __shared__ float Pt [EDIM * 36];   // Pt[d][s'] 32+pad
    __shared__ float WvT[EDIM * 68];   // WvT[d][e]
    __shared__ float wsh[32];

    const int b  = blockIdx.x;
    const int hB = blockIdx.y;         // slot half
    const int sB = hB * 32;
    const int tid = threadIdx.x;

    for (int i = tid; i < 32 * EDIM; i += 256) {
        const int sp = i >> 6, d = i & 63;
        float p = 0.f;
        #pragma unroll
        for (int k = 0; k < BPB; k++)
            p += g_Ppart[((size_t)(k * BATCH + b)) * SLOTS * EDIM + (sB + sp) * EDIM + d];
        Pt[d * 36 + sp] = p;
    }
    for (int i = tid; i < EDIM * EDIM; i += 256) {
        const int e = i >> 6, d = i & 63;
        WvT[d * 68 + e] = Wv[i];
    }
    if (tid < 32) {
        float w = 0.f;
        #pragma unroll
        for (int k = 0; k < BPB; k++)
            w += g_Wpart[(k * BATCH + b) * SLOTS + sB + tid];
        wsh[tid] = w;
    }
    __syncthreads();

    const int ty = tid >> 4;    // 0..15 -> 2 slots each
    const int tx = tid & 15;    // 0..15 -> 4 e each
    float acc[2][4];
    #pragma unroll
    for (int i = 0; i < 2; i++)
        #pragma unroll
        for (int j = 0; j < 4; j++) acc[i][j] = 0.0f;

    #pragma unroll 8
    for (int d = 0; d < EDIM; d++) {
        const float p0 = Pt[d * 36 + ty * 2];
        const float p1 = Pt[d * 36 + ty * 2 + 1];
        const float4 w4 = *(const float4*)&WvT[d * 68 + tx * 4];
        acc[0][0] += p0 * w4.x; acc[0][1] += p0 * w4.y;
        acc[0][2] += p0 * w4.z; acc[0][3] += p0 * w4.w;
        acc[1][0] += p1 * w4.x; acc[1][1] += p1 * w4.y;
        acc[1][2] += p1 * w4.z; acc[1][3] += p1 * w4.w;
    }

    #pragma unroll
    for (int i = 0; i < 2; i++) {
        const int s = sB + ty * 2 + i;
        const float wv = wsh[ty * 2 + i];
        const float em = __expf(-wv);                     // 1-g
        const float sc = (1.0f - em) / fmaxf(wv, 1e-6f);  // g/max(W,1e-6)
        const float4 m4 = ((const float4*)mv)[((size_t)b * SLOTS + s) * 16 + tx];
        float4 o;
        o.x = m4.x * em + acc[i][0] * sc;
        o.y = m4.y * em + acc[i][1] * sc;
        o.z = m4.z * em + acc[i][2] * sc;
        o.w = m4.w * em + acc[i][3] * sc;
        ((float4*)out)[((size_t)b * SLOTS + s) * 16 + tx] = o;
    }
}

// ============================================================
extern "C" void kernel_launch(void* const* d_in, const int* in_sizes, int n_in,
                              void* d_out, int out_size) {
    const float* x  = (const float*)d_in[0];
    const float* ma = (const float*)d_in[1];
    const float* mv = (const float*)d_in[2];
    const float* Wq = (const float*)d_in[3];
    const float* Wv = (const float*)d_in[4];
    const float* Wg = (const float*)d_in[5];
    const float* bg = (const float*)d_in[6];
    float* out = (float*)d_out;
    (void)in_sizes; (void)n_in; (void)out_size;

    cudaFuncSetAttribute(main_kernel,
                         cudaFuncAttributeMaxDynamicSharedMemorySize, SM_BYTES);

    dim3 grid(BPB, BATCH);
    main_kernel<<<grid, 256, SM_BYTES>>>(x, ma, Wq, Wg, bg);
    dim3 fgrid(BATCH, 2);
    finalize_kernel<<<fgrid, 256>>>(mv, Wv, out);
}